// round 4
// baseline (speedup 1.0000x reference)
#include <cuda_runtime.h>

// Single-CTA pitch loss: zero cross-block communication.
//
// 1024 threads = 128 eight-lane groups. Group g handles notes g, g+128, ...,
// g+896 (8 notes). For each note, lane `sub` loads ONE float4 from each track
// (warp-level access = 512B contiguous per track -> fully coalesced), the
// 8-lane group reduces the gen-t diff sum with 3 width-8 shuffles, and the
// group leader tests |sum| > 0.5 * len (no division). Leaders accumulate hit
// counts in registers; REDUX collapses them per warp, smem + REDUX collapse
// across warps, and thread 0 writes the scalar loss. One kernel node, no
// atomics, no fences, no cluster -> deterministic and replay-cheap.
__global__ void __launch_bounds__(1024, 1)
pitch_loss_oneblock_kernel(const float* __restrict__ gen_f0,
                           const float* __restrict__ t_f0,
                           const int*   __restrict__ onset,
                           const int*   __restrict__ offset,
                           float*       __restrict__ out,
                           int N) {
    __shared__ int warp_counts[32];

    const int tid  = threadIdx.x;
    const int lane = tid & 31;
    const int warp = tid >> 5;
    const int sub  = tid & 7;     // lane within 8-lane note group
    const int grp  = tid >> 3;    // group id, 0..127

    const int ngroups = blockDim.x >> 3;   // 128
    int hits = 0;

    for (int note = grp; note < N; note += ngroups) {
        int a = onset[note];
        int b = offset[note];
        int len = b - a;

        float d = 0.0f;
        if (len == 32 && (a & 3) == 0) {
            // Fast path: 32-frame segment, 16B-aligned. One float4 per lane
            // per track covers the whole segment.
            const float4* g4 = (const float4*)(gen_f0 + a);
            const float4* t4 = (const float4*)(t_f0  + a);
            float4 g = g4[sub];
            float4 t = t4[sub];
            d = ((g.x - t.x) + (g.y - t.y)) + ((g.z - t.z) + (g.w - t.w));
        } else {
            // General path: strided scalar loads over the segment.
            for (int i = a + sub; i < b; i += 8)
                d += gen_f0[i] - t_f0[i];
        }

        // Width-8 reduce; lane sub==0 of the group holds the note sum.
        #pragma unroll
        for (int o = 4; o > 0; o >>= 1)
            d += __shfl_down_sync(0xFFFFFFFFu, d, o, 8);

        if (sub == 0 && fabsf(d) > 0.5f * (float)len)
            hits++;
    }

    // Collapse hit counts: warp-level REDUX (non-leaders contribute 0).
    int wsum = __reduce_add_sync(0xFFFFFFFFu, (unsigned)hits);
    if (lane == 0) warp_counts[warp] = wsum;
    __syncthreads();

    if (warp == 0) {
        int v = warp_counts[lane];   // blockDim = 1024 -> exactly 32 warps
        int total = __reduce_add_sync(0xFFFFFFFFu, (unsigned)v);
        if (lane == 0)
            out[0] = (float)total / (float)N;
    }
}

extern "C" void kernel_launch(void* const* d_in, const int* in_sizes, int n_in,
                              void* d_out, int out_size) {
    const float* gen_f0 = (const float*)d_in[0];
    const float* t_f0   = (const float*)d_in[1];
    const int*   onset  = (const int*)d_in[2];
    const int*   offset = (const int*)d_in[3];
    float* out = (float*)d_out;

    int N = in_sizes[2];   // number of notes (1024)

    pitch_loss_oneblock_kernel<<<1, 1024>>>(gen_f0, t_f0, onset, offset, out, N);
}

// round 5
// speedup vs baseline: 1.6522x; 1.6522x over previous
#include <cuda_runtime.h>

// Single-node pitch loss.
//
// One warp per note (grid 128 x 256 = 1024 warps). Each lane loads one frame
// per track (coalesced 128B per warp per track), the warp reduces the gen-t
// DIFFERENCE (5 shuffles), and the leader tests |sum| > 0.5*len (no division).
//
// Cross-CTA combine without a second kernel, fence, or poll:
// a single 64-bit accumulator packs (hits << 32) | notes_done. Every note's
// leader atomically adds its contribution; the add whose RETURNED low word is
// N-1 is the last arriver and already holds the final hit total in the return
// value. It writes the loss and swaps the accumulator back to 0 (all N adds
// are serialized before it, so the reset is race-free and the kernel is
// deterministic across graph replays; the integer sum is order-independent).
__device__ unsigned long long g_acc = 0ull;

__global__ void __launch_bounds__(256, 1)
pitch_loss_kernel(const float* __restrict__ gen_f0,
                  const float* __restrict__ t_f0,
                  const int*   __restrict__ onset,
                  const int*   __restrict__ offset,
                  float*       __restrict__ out,
                  int N) {
    const int gwarp = (blockIdx.x * blockDim.x + threadIdx.x) >> 5;
    const int lane  = threadIdx.x & 31;
    if (gwarp >= N) return;

    const int a = onset[gwarp];
    const int b = offset[gwarp];

    float d = 0.0f;
    for (int i = a + lane; i < b; i += 32)
        d += gen_f0[i] - t_f0[i];

    #pragma unroll
    for (int o = 16; o > 0; o >>= 1)
        d += __shfl_down_sync(0xFFFFFFFFu, d, o);

    if (lane == 0) {
        unsigned long long hit =
            (fabsf(d) > 0.5f * (float)(b - a)) ? 1ull : 0ull;

        unsigned long long old =
            atomicAdd(&g_acc, (hit << 32) | 1ull);

        if ((unsigned)(old & 0xFFFFFFFFull) == (unsigned)(N - 1)) {
            unsigned total = (unsigned)(old >> 32) + (unsigned)hit;
            out[0] = (float)total / (float)N;
            atomicExch(&g_acc, 0ull);   // reset for the next graph replay
        }
    }
}

extern "C" void kernel_launch(void* const* d_in, const int* in_sizes, int n_in,
                              void* d_out, int out_size) {
    const float* gen_f0 = (const float*)d_in[0];
    const float* t_f0   = (const float*)d_in[1];
    const int*   onset  = (const int*)d_in[2];
    const int*   offset = (const int*)d_in[3];
    float* out = (float*)d_out;

    const int N = in_sizes[2];   // number of notes (1024)

    const int THREADS = 256;                       // 8 warps per block
    const int blocks  = (N * 32 + THREADS - 1) / THREADS;   // 128
    pitch_loss_kernel<<<blocks, THREADS>>>(gen_f0, t_f0, onset, offset, out, N);
}